// round 5
// baseline (speedup 1.0000x reference)
#include <cuda_runtime.h>
#include <cuda_bf16.h>

// Problem constants
#define B 32
#define C 3
#define H 640
#define W 640
#define POOL 8
#define CELL 80              // H/POOL
#define HIDDEN 64
#define FEAT (C*POOL*POOL)   // 192
#define NPARAM 15
#define PLANE (H*W)          // 409600
#define PLANE4 (PLANE/4)     // 102400
#define W4 (W/4)             // 160

#define NCELLS (B * C * POOL * POOL)      // 6144
#define CELLS_PER_BLOCK 4
// INVARIANT: POOL_BLOCKS * CELLS_PER_BLOCK == NCELLS (grid must cover all cells)
#define POOL_BLOCKS (NCELLS / CELLS_PER_BLOCK)   // 1536

// Scratch (allocation-free rule: __device__ globals)
__device__ float g_feat[B * FEAT];
__device__ float g_params[B * 16];

// ---------------------------------------------------------------------------
// Kernel 1: adaptive avg pool 640x640 -> 8x8 per (b,c).
// 2 warps per 80x80 cell (40 rows each), float4 loads, 4 accumulators.
// Grid: 6144 cells / 4 cells-per-block = 1536 blocks x 256 threads.
// ---------------------------------------------------------------------------
__global__ __launch_bounds__(256) void pool_kernel(const float* __restrict__ x,
                                                   float* __restrict__ feat) {
    const int warp = threadIdx.x >> 5;
    const int lane = threadIdx.x & 31;
    const int gcell = blockIdx.x * CELLS_PER_BLOCK + (warp >> 1);   // 0..6143
    const int half  = warp & 1;                        // top/bottom 40 rows

    const int pc = gcell & 7;
    const int pr = (gcell >> 3) & 7;
    const int bc = gcell >> 6;                         // b*C + c

    const float4* base = (const float4*)x + (size_t)bc * PLANE4
         + (size_t)(pr * CELL + half * 40) * W4 + pc * 20;

    // 40 rows x 20 float4 = 800 float4, 25 iterations of 32 lanes
    float4 a0 = make_float4(0.f, 0.f, 0.f, 0.f);
    float4 a1 = make_float4(0.f, 0.f, 0.f, 0.f);
    float4 a2 = make_float4(0.f, 0.f, 0.f, 0.f);
    float4 a3 = make_float4(0.f, 0.f, 0.f, 0.f);
    #pragma unroll 5
    for (int it = 0; it < 25; ++it) {
        int idx = it * 32 + lane;          // 0..799
        int r = idx / 20;
        int col = idx - r * 20;
        float4 v = base[(size_t)r * W4 + col];
        if ((it & 3) == 0)      { a0.x += v.x; a0.y += v.y; a0.z += v.z; a0.w += v.w; }
        else if ((it & 3) == 1) { a1.x += v.x; a1.y += v.y; a1.z += v.z; a1.w += v.w; }
        else if ((it & 3) == 2) { a2.x += v.x; a2.y += v.y; a2.z += v.z; a2.w += v.w; }
        else                    { a3.x += v.x; a3.y += v.y; a3.z += v.z; a3.w += v.w; }
    }
    float s = (a0.x + a0.y + a0.z + a0.w) + (a1.x + a1.y + a1.z + a1.w)
            + (a2.x + a2.y + a2.z + a2.w) + (a3.x + a3.y + a3.z + a3.w);
    #pragma unroll
    for (int o = 16; o; o >>= 1) s += __shfl_xor_sync(0xFFFFFFFFu, s, o);

    __shared__ float sm[8];
    if (lane == 0) sm[warp] = s;
    __syncthreads();
    if (threadIdx.x < CELLS_PER_BLOCK) {
        float tot = sm[2 * threadIdx.x] + sm[2 * threadIdx.x + 1];
        // feat index == gcell for this cell: bc*64 + pr*8 + pc
        feat[blockIdx.x * CELLS_PER_BLOCK + threadIdx.x] = tot * (1.f / (CELL * CELL));
    }
}

// ---------------------------------------------------------------------------
// Kernel 2: per-sample MLP (unchanged; ~2-3us, not a bottleneck)
// ---------------------------------------------------------------------------
__global__ __launch_bounds__(64) void mlp_kernel(const float* __restrict__ feat,
                                                 const float* __restrict__ W1,
                                                 const float* __restrict__ b1,
                                                 const float* __restrict__ W2,
                                                 float* __restrict__ params) {
    int b = blockIdx.x;
    int j = threadIdx.x;
    __shared__ float fs[FEAT];
    __shared__ float hs[HIDDEN];

    for (int k = j; k < FEAT; k += HIDDEN) fs[k] = feat[b * FEAT + k];
    __syncthreads();

    float acc = b1[j];
    #pragma unroll 8
    for (int k = 0; k < FEAT; ++k) acc = fmaf(fs[k], W1[k * HIDDEN + j], acc);
    hs[j] = fminf(fmaxf(acc, 0.f), 6.f);
    __syncthreads();

    if (j < NPARAM) {
        float a = 0.f;
        #pragma unroll 8
        for (int k = 0; k < HIDDEN; ++k) a = fmaf(hs[k], W2[k * NPARAM + j], a);
        params[b * 16 + j] = 1.f / (1.f + __expf(-a));
    }
}

// ---------------------------------------------------------------------------
// Kernel 3: per-pixel 3x3 color transform + gamma pow + normalize.
// 2 float4-groups per thread (ILP for MUFU latency). Blocks iterate in
// REVERSE address order so the L2-resident tail of x from the pool pass
// is reused before eviction.
// ---------------------------------------------------------------------------
#define CHUNKS_PER_IMG 200   // PLANE4 / 512

__global__ __launch_bounds__(256) void transform_kernel(const float* __restrict__ x,
                                                        const float* __restrict__ params,
                                                        float* __restrict__ out) {
    const int rev = (B * CHUNKS_PER_IMG - 1) - blockIdx.x;  // reversed order
    const int b   = rev / CHUNKS_PER_IMG;
    const int blk = rev - b * CHUNKS_PER_IMG;

    __shared__ float p[16];
    if (threadIdx.x < 16) p[threadIdx.x] = params[b * 16 + threadIdx.x];
    __syncthreads();

    const float m00 = p[0], m01 = p[1], m02 = p[2];
    const float m10 = p[3], m11 = p[4], m12 = p[5];
    const float m20 = p[6], m21 = p[7], m22 = p[8];
    const float bi0 = p[9], bi1 = p[10], bi2 = p[11];
    const float g0  = p[12], g1 = p[13], g2 = p[14];

    const float s0 = 1.0f / 0.229f, s1 = 1.0f / 0.224f, s2 = 1.0f / 0.225f;
    const float t0 = -0.485f / 0.229f, t1 = -0.456f / 0.224f, t2 = -0.406f / 0.225f;

    const int i4a = blk * 512 + threadIdx.x;        // first float4 index
    const int i4b = i4a + 256;                      // second float4 index
    const float4* xb = (const float4*)(x + (size_t)b * C * PLANE);
    float4* ob = (float4*)(out + (size_t)b * C * PLANE);

    // 6 independent loads up front (MLP)
    float4 xa0 = xb[i4a];
    float4 xc0 = xb[i4a + PLANE4];
    float4 xd0 = xb[i4a + 2 * PLANE4];
    float4 xa1 = xb[i4b];
    float4 xc1 = xb[i4b + PLANE4];
    float4 xd1 = xb[i4b + 2 * PLANE4];

    float4 o00, o10, o20, o01, o11, o21;
    #define DO_ELEM(XA, XC, XD, O0, O1, O2, FLD)                                   \
    {                                                                              \
        float a = XA.FLD, bch = XC.FLD, cch = XD.FLD;                              \
        float y0 = fmaf(m00, a, fmaf(m01, bch, fmaf(m02, cch, bi0)));              \
        float y1 = fmaf(m10, a, fmaf(m11, bch, fmaf(m12, cch, bi1)));              \
        float y2 = fmaf(m20, a, fmaf(m21, bch, fmaf(m22, cch, bi2)));              \
        y0 = fmaxf(y0, 1e-20f); y1 = fmaxf(y1, 1e-20f); y2 = fmaxf(y2, 1e-20f);    \
        O0.FLD = fmaf(__powf(y0, g0), s0, t0);                                     \
        O1.FLD = fmaf(__powf(y1, g1), s1, t1);                                     \
        O2.FLD = fmaf(__powf(y2, g2), s2, t2);                                     \
    }
    DO_ELEM(xa0, xc0, xd0, o00, o10, o20, x)
    DO_ELEM(xa1, xc1, xd1, o01, o11, o21, x)
    DO_ELEM(xa0, xc0, xd0, o00, o10, o20, y)
    DO_ELEM(xa1, xc1, xd1, o01, o11, o21, y)
    DO_ELEM(xa0, xc0, xd0, o00, o10, o20, z)
    DO_ELEM(xa1, xc1, xd1, o01, o11, o21, z)
    DO_ELEM(xa0, xc0, xd0, o00, o10, o20, w)
    DO_ELEM(xa1, xc1, xd1, o01, o11, o21, w)
    #undef DO_ELEM

    ob[i4a]              = o00;
    ob[i4a + PLANE4]     = o10;
    ob[i4a + 2 * PLANE4] = o20;
    ob[i4b]              = o01;
    ob[i4b + PLANE4]     = o11;
    ob[i4b + 2 * PLANE4] = o21;
}

// ---------------------------------------------------------------------------
extern "C" void kernel_launch(void* const* d_in, const int* in_sizes, int n_in,
                              void* d_out, int out_size) {
    const float* x  = (const float*)d_in[0];   // (32,3,640,640)
    const float* W1 = (const float*)d_in[1];   // (192,64)
    const float* b1 = (const float*)d_in[2];   // (64,)
    const float* W2 = (const float*)d_in[3];   // (64,15)
    float* out = (float*)d_out;

    float* feat;   cudaGetSymbolAddress((void**)&feat,   g_feat);
    float* params; cudaGetSymbolAddress((void**)&params, g_params);

    pool_kernel<<<POOL_BLOCKS, 256>>>(x, feat);        // 1536 blocks
    mlp_kernel<<<B, HIDDEN>>>(feat, W1, b1, W2, params);
    transform_kernel<<<B * CHUNKS_PER_IMG, 256>>>(x, params, out);
}

// round 6
// speedup vs baseline: 1.0594x; 1.0594x over previous
#include <cuda_runtime.h>
#include <cuda_bf16.h>

// Problem constants
#define B 32
#define C 3
#define H 640
#define W 640
#define POOL 8
#define CELL 80              // H/POOL
#define HIDDEN 64
#define FEAT (C*POOL*POOL)   // 192
#define NPARAM 15
#define PLANE (H*W)          // 409600
#define PLANE4 (PLANE/4)     // 102400

// Scratch (allocation-free rule: __device__ globals)
__device__ float g_feat[B * FEAT];
__device__ float g_params[B * 16];

// ---------------------------------------------------------------------------
// Kernel 1: adaptive avg pool 640x640 -> 8x8 per (b,c).  (round-0 design,
// proven 34 us / 58% DRAM: one warp per 80x80 cell, coalesced scalar loads)
// One block per (b, c, pool_row); 8 warps = 8 pool cols.
// ---------------------------------------------------------------------------
__global__ __launch_bounds__(256) void pool_kernel(const float* __restrict__ x,
                                                   float* __restrict__ feat) {
    int bid  = blockIdx.x;            // 0 .. B*C*POOL-1
    int pr   = bid & 7;
    int c    = (bid >> 3) % C;
    int b    = bid / (C * POOL);
    int warp = threadIdx.x >> 5;      // = pool col (pc)
    int lane = threadIdx.x & 31;

    const float* base = x + (((size_t)b * C + c) * H + (size_t)pr * CELL) * W
                        + (size_t)warp * CELL;
    const bool tail = (lane < 16);
    float s = 0.f;
    #pragma unroll 4
    for (int r = 0; r < CELL; ++r) {
        const float* rp = base + (size_t)r * W;
        s += rp[lane];
        s += rp[lane + 32];
        if (tail) s += rp[lane + 64];
    }
    #pragma unroll
    for (int o = 16; o; o >>= 1) s += __shfl_xor_sync(0xFFFFFFFFu, s, o);
    if (lane == 0)
        feat[(b * C + c) * (POOL * POOL) + pr * POOL + warp] = s * (1.f / (CELL * CELL));
}

// ---------------------------------------------------------------------------
// Kernel 2: per-sample MLP (unchanged; ~2-3us, not a bottleneck)
// ---------------------------------------------------------------------------
__global__ __launch_bounds__(64) void mlp_kernel(const float* __restrict__ feat,
                                                 const float* __restrict__ W1,
                                                 const float* __restrict__ b1,
                                                 const float* __restrict__ W2,
                                                 float* __restrict__ params) {
    int b = blockIdx.x;
    int j = threadIdx.x;
    __shared__ float fs[FEAT];
    __shared__ float hs[HIDDEN];

    for (int k = j; k < FEAT; k += HIDDEN) fs[k] = feat[b * FEAT + k];
    __syncthreads();

    float acc = b1[j];
    #pragma unroll 8
    for (int k = 0; k < FEAT; ++k) acc = fmaf(fs[k], W1[k * HIDDEN + j], acc);
    hs[j] = fminf(fmaxf(acc, 0.f), 6.f);
    __syncthreads();

    if (j < NPARAM) {
        float a = 0.f;
        #pragma unroll 8
        for (int k = 0; k < HIDDEN; ++k) a = fmaf(hs[k], W2[k * NPARAM + j], a);
        params[b * 16 + j] = 1.f / (1.f + __expf(-a));
    }
}

// ---------------------------------------------------------------------------
// Kernel 3: per-pixel 3x3 color transform + gamma pow + normalize.
// KEY CHANGE vs best: streaming memory policy.
//   - stores use __stcs (evict-first) so the 157MB output stream does NOT
//     evict the pool-warmed x lines from L2
//   - x loads use __ldcs (read-once)
//   - blocks iterate in reverse address order to harvest the L2-resident
//     tail of x left by the pool pass
// 2 float4-groups per thread for MUFU-latency ILP.
// ---------------------------------------------------------------------------
#define CHUNKS_PER_IMG 200   // PLANE4 / 512

__global__ __launch_bounds__(256) void transform_kernel(const float* __restrict__ x,
                                                        const float* __restrict__ params,
                                                        float* __restrict__ out) {
    const int rev = (B * CHUNKS_PER_IMG - 1) - blockIdx.x;  // reversed order
    const int b   = rev / CHUNKS_PER_IMG;
    const int blk = rev - b * CHUNKS_PER_IMG;

    __shared__ float p[16];
    if (threadIdx.x < 16) p[threadIdx.x] = params[b * 16 + threadIdx.x];
    __syncthreads();

    const float m00 = p[0], m01 = p[1], m02 = p[2];
    const float m10 = p[3], m11 = p[4], m12 = p[5];
    const float m20 = p[6], m21 = p[7], m22 = p[8];
    const float bi0 = p[9], bi1 = p[10], bi2 = p[11];
    const float g0  = p[12], g1 = p[13], g2 = p[14];

    const float s0 = 1.0f / 0.229f, s1 = 1.0f / 0.224f, s2 = 1.0f / 0.225f;
    const float t0 = -0.485f / 0.229f, t1 = -0.456f / 0.224f, t2 = -0.406f / 0.225f;

    const int i4a = blk * 512 + threadIdx.x;
    const int i4b = i4a + 256;
    const float4* xb = (const float4*)(x + (size_t)b * C * PLANE);
    float4* ob = (float4*)(out + (size_t)b * C * PLANE);

    // 6 independent read-once loads up front (MLP)
    float4 xa0 = __ldcs(xb + i4a);
    float4 xc0 = __ldcs(xb + i4a + PLANE4);
    float4 xd0 = __ldcs(xb + i4a + 2 * PLANE4);
    float4 xa1 = __ldcs(xb + i4b);
    float4 xc1 = __ldcs(xb + i4b + PLANE4);
    float4 xd1 = __ldcs(xb + i4b + 2 * PLANE4);

    float4 o00, o10, o20, o01, o11, o21;
    #define DO_ELEM(XA, XC, XD, O0, O1, O2, FLD)                                   \
    {                                                                              \
        float a = XA.FLD, bch = XC.FLD, cch = XD.FLD;                              \
        float y0 = fmaf(m00, a, fmaf(m01, bch, fmaf(m02, cch, bi0)));              \
        float y1 = fmaf(m10, a, fmaf(m11, bch, fmaf(m12, cch, bi1)));              \
        float y2 = fmaf(m20, a, fmaf(m21, bch, fmaf(m22, cch, bi2)));              \
        y0 = fmaxf(y0, 1e-20f); y1 = fmaxf(y1, 1e-20f); y2 = fmaxf(y2, 1e-20f);    \
        O0.FLD = fmaf(__powf(y0, g0), s0, t0);                                     \
        O1.FLD = fmaf(__powf(y1, g1), s1, t1);                                     \
        O2.FLD = fmaf(__powf(y2, g2), s2, t2);                                     \
    }
    DO_ELEM(xa0, xc0, xd0, o00, o10, o20, x)
    DO_ELEM(xa1, xc1, xd1, o01, o11, o21, x)
    DO_ELEM(xa0, xc0, xd0, o00, o10, o20, y)
    DO_ELEM(xa1, xc1, xd1, o01, o11, o21, y)
    DO_ELEM(xa0, xc0, xd0, o00, o10, o20, z)
    DO_ELEM(xa1, xc1, xd1, o01, o11, o21, z)
    DO_ELEM(xa0, xc0, xd0, o00, o10, o20, w)
    DO_ELEM(xa1, xc1, xd1, o01, o11, o21, w)
    #undef DO_ELEM

    // evict-first streaming stores: don't displace x in L2
    __stcs(ob + i4a,              o00);
    __stcs(ob + i4a + PLANE4,     o10);
    __stcs(ob + i4a + 2 * PLANE4, o20);
    __stcs(ob + i4b,              o01);
    __stcs(ob + i4b + PLANE4,     o11);
    __stcs(ob + i4b + 2 * PLANE4, o21);
}

// ---------------------------------------------------------------------------
extern "C" void kernel_launch(void* const* d_in, const int* in_sizes, int n_in,
                              void* d_out, int out_size) {
    const float* x  = (const float*)d_in[0];   // (32,3,640,640)
    const float* W1 = (const float*)d_in[1];   // (192,64)
    const float* b1 = (const float*)d_in[2];   // (64,)
    const float* W2 = (const float*)d_in[3];   // (64,15)
    float* out = (float*)d_out;

    float* feat;   cudaGetSymbolAddress((void**)&feat,   g_feat);
    float* params; cudaGetSymbolAddress((void**)&params, g_params);

    pool_kernel<<<B * C * POOL, 256>>>(x, feat);        // 768 blocks (round-0)
    mlp_kernel<<<B, HIDDEN>>>(feat, W1, b1, W2, params);
    transform_kernel<<<B * CHUNKS_PER_IMG, 256>>>(x, params, out);
}